// round 11
// baseline (speedup 1.0000x reference)
#include <cuda_runtime.h>
#include <cuda_fp16.h>
#include <cstdint>
#include <cstddef>

#define DD 4096
#define MM 8192

// Scratch: Hadamard-rotated fp16 W [N,K]; fp16 x [M,K]; per-row done flags.
__device__ __align__(256) __half g_Wh[(size_t)DD * DD];
__device__ __align__(256) __half g_Xh[(size_t)MM * DD];
__device__ unsigned g_wflag[DD];   // epoch counter per W row (monotonic)
__device__ unsigned g_xflag[MM];   // epoch counter per x row (monotonic)

// ---------------------------------------------------------------------------
// Fused persistent kernel:
//   phase 1 (per CTA): WHT-rotate owned W rows -> g_Wh, convert owned x rows
//                      -> g_Xh, publish per-row flags (epoch = old+1).
//   phase 2 (per CTA): fp16 mma.sync GEMM over tiles c, c+GRID, ... ; before
//                      each tile spin on the 128 W-row + 128 x-row flags.
// (xH)W^T == x(WH)^T since H is symmetric. GEMM: CTA 128x128, 4 warps (2x2),
// warp tile 64x64, TKH=64, 3-stage cp.async, XOR-swizzled smem, 2 CTAs/SM.
// ---------------------------------------------------------------------------
constexpr int TM = 128;
constexpr int TN = 128;
constexpr int TKH = 64;                      // halves per K-tile (128 B)
constexpr int NKT = DD / TKH;                // 64
constexpr int STAGES = 3;
constexpr int A_BYTES = TM * 128;            // 16384
constexpr int B_BYTES = TN * 128;            // 16384
constexpr int STAGE_BYTES = A_BYTES + B_BYTES;          // 32768
constexpr int SMEM_TOTAL = STAGES * STAGE_BYTES;        // 98304
constexpr int NTHREADS = 128;
constexpr int NTILES = (MM / TM) * (DD / TN);           // 2048
constexpr int GRID = 296;                               // 148 SMs x 2

__device__ __forceinline__ uint32_t smem_u32(const void* p) {
    return (uint32_t)__cvta_generic_to_shared(p);
}
__device__ __forceinline__ void cp16(uint32_t dst, const void* src) {
    asm volatile("cp.async.cg.shared.global [%0], [%1], 16;\n" :: "r"(dst), "l"(src));
}
__device__ __forceinline__ void ldsm4(uint32_t* r, uint32_t addr) {
    asm volatile("ldmatrix.sync.aligned.m8n8.x4.shared.b16 {%0,%1,%2,%3}, [%4];"
                 : "=r"(r[0]), "=r"(r[1]), "=r"(r[2]), "=r"(r[3]) : "r"(addr));
}
__device__ __forceinline__ void mma_f16(float* c, const uint32_t* a, const uint32_t* b) {
    asm volatile(
        "mma.sync.aligned.m16n8k16.row.col.f32.f16.f16.f32 "
        "{%0,%1,%2,%3}, {%4,%5,%6,%7}, {%8,%9}, {%0,%1,%2,%3};"
        : "+f"(c[0]), "+f"(c[1]), "+f"(c[2]), "+f"(c[3])
        : "r"(a[0]), "r"(a[1]), "r"(a[2]), "r"(a[3]),
          "r"(b[0]), "r"(b[1]));
}

// swizzled byte offset inside a 128B-wide tile
__device__ __forceinline__ uint32_t sw_off(int row, int chunk) {
    return (uint32_t)(row * 128 + ((chunk ^ (row & 7)) << 4));
}

// tile id -> (m0, n0) with G=16 M-group swizzle for L2 locality
__device__ __forceinline__ void tile_mn(int pid, int& m0, int& n0) {
    constexpr int PN = DD / TN;           // 32
    constexpr int G = 16;
    const int grp = pid / (G * PN);
    const int pm = grp * G + (pid % G);
    const int pn = (pid % (G * PN)) / G;
    m0 = pm * TM;
    n0 = pn * TN;
}

__device__ __forceinline__ void issue_stage(int m0, int n0, int kt, int slot,
                                            uint32_t sbase, int tid) {
    const uint32_t stA = sbase + (uint32_t)(slot * STAGE_BYTES);
    const uint32_t stB = stA + A_BYTES;
    const __half* gA = g_Xh + (size_t)m0 * DD + kt * TKH;
    const __half* gB = g_Wh + (size_t)n0 * DD + kt * TKH;
#pragma unroll
    for (int i = 0; i < 8; ++i) {            // A: 1024 16B chunks
        const int idx = tid + i * NTHREADS;
        const int row = idx >> 3;
        const int c = idx & 7;
        cp16(stA + sw_off(row, c), gA + (size_t)row * DD + c * 8);
    }
#pragma unroll
    for (int i = 0; i < 8; ++i) {            // B: 1024 16B chunks
        const int idx = tid + i * NTHREADS;
        const int row = idx >> 3;
        const int c = idx & 7;
        cp16(stB + sw_off(row, c), gB + (size_t)row * DD + c * 8);
    }
    asm volatile("cp.async.commit_group;\n" ::: "memory");
}

__global__ void __launch_bounds__(NTHREADS, 2)
fused_kernel(const float* __restrict__ W, const float* __restrict__ x,
             const float* __restrict__ bias, float* __restrict__ out) {
    extern __shared__ char smem[];
    __shared__ unsigned sTgt;
    const uint32_t sbase = smem_u32(smem);
    const int tid = threadIdx.x;
    const int lane = tid & 31;
    const int c = blockIdx.x;

    // ---------------- phase 1: prep (owned rows) ----------------
    if (tid == 0) sTgt = *(volatile unsigned*)&g_wflag[c] + 1u;
    __syncthreads();
    const unsigned tgt = sTgt;

    // WHT of owned W rows (128 threads, 32 elems/thread)
    {
        float* sh = (float*)smem;
        for (int r = c; r < DD; r += GRID) {
            float v[32];
            const float4* src = (const float4*)(W + (size_t)r * DD) + tid * 8;
#pragma unroll
            for (int j = 0; j < 8; ++j) {
                float4 u = src[j];
                v[4 * j] = u.x; v[4 * j + 1] = u.y;
                v[4 * j + 2] = u.z; v[4 * j + 3] = u.w;
            }
            // stages len=1..16: in registers (elements contiguous per thread)
#pragma unroll
            for (int len = 1; len <= 16; len <<= 1) {
#pragma unroll
                for (int e = 0; e < 32; ++e) {
                    if ((e & len) == 0) {
                        float a = v[e], b = v[e | len];
                        v[e] = a + b;
                        v[e | len] = a - b;
                    }
                }
            }
            // stages len=32..512: shfl.bfly across lanes
#pragma unroll
            for (int m = 1; m <= 16; m <<= 1) {
#pragma unroll
                for (int e = 0; e < 32; ++e) {
                    float rr = __shfl_xor_sync(0xffffffffu, v[e], m);
                    v[e] = (lane & m) ? (rr - v[e]) : (v[e] + rr);
                }
            }
            // stages len=1024,2048: cross-warp via smem
#pragma unroll
            for (int mw = 32; mw <= 64; mw <<= 1) {
                __syncthreads();
#pragma unroll
                for (int e = 0; e < 32; ++e) sh[tid * 32 + e] = v[e];
                __syncthreads();
                const int p = (tid ^ mw) * 32;
#pragma unroll
                for (int e = 0; e < 32; ++e) {
                    float rr = sh[p + e];
                    v[e] = (tid & mw) ? (rr - v[e]) : (v[e] + rr);
                }
            }
            // scale, convert, store 32 halves (4x uint4)
            uint4* dst = (uint4*)(g_Wh + (size_t)r * DD + tid * 32);
#pragma unroll
            for (int j = 0; j < 4; ++j) {
                __half2 h0 = __floats2half2_rn(v[8 * j] * 0.015625f, v[8 * j + 1] * 0.015625f);
                __half2 h1 = __floats2half2_rn(v[8 * j + 2] * 0.015625f, v[8 * j + 3] * 0.015625f);
                __half2 h2 = __floats2half2_rn(v[8 * j + 4] * 0.015625f, v[8 * j + 5] * 0.015625f);
                __half2 h3 = __floats2half2_rn(v[8 * j + 6] * 0.015625f, v[8 * j + 7] * 0.015625f);
                uint4 o;
                o.x = *(uint32_t*)&h0; o.y = *(uint32_t*)&h1;
                o.z = *(uint32_t*)&h2; o.w = *(uint32_t*)&h3;
                dst[j] = o;
            }
            __threadfence();
            __syncthreads();
            if (tid == 0) *(volatile unsigned*)&g_wflag[r] = tgt;
        }
    }

    // convert owned x rows to fp16
    for (int r = c; r < MM; r += GRID) {
        const float4* xs = (const float4*)(x + (size_t)r * DD);
        uint2* dst = (uint2*)(g_Xh + (size_t)r * DD);
#pragma unroll
        for (int i = 0; i < 8; ++i) {
            const int j = tid + i * NTHREADS;
            float4 u = xs[j];
            __half2 h0 = __floats2half2_rn(u.x, u.y);
            __half2 h1 = __floats2half2_rn(u.z, u.w);
            uint2 o;
            o.x = *(uint32_t*)&h0; o.y = *(uint32_t*)&h1;
            dst[j] = o;
        }
        __threadfence();
        __syncthreads();
        if (tid == 0) *(volatile unsigned*)&g_xflag[r] = tgt;
    }

    // ---------------- phase 2: GEMM ----------------
    const int wid = tid >> 5;
    const int g = lane >> 2;              // accumulator row within 8
    const int nc2 = (lane & 3) * 2;       // accumulator n-col base
    const int wm = wid & 1;               // 2 warps along M (64 rows each)
    const int wn = wid >> 1;              // 2 warps along N (64 cols each)
    const int a_row = lane & 15;
    const int a_cofs = lane >> 4;                       // 0/1
    const int b_row = ((lane >> 4) << 3) + (lane & 7);
    const int b_cofs = (lane >> 3) & 1;                 // 0/1

    for (int t = c; t < NTILES; t += GRID) {
        int m0, n0;
        tile_mn(t, m0, n0);

        // wait for the 128 W rows and 128 x rows of this tile
        {
            volatile unsigned* wf = (volatile unsigned*)&g_wflag[n0 + tid];
            volatile unsigned* xf = (volatile unsigned*)&g_xflag[m0 + tid];
            while (*wf < tgt) {}
            while (*xf < tgt) {}
            __threadfence();
        }
        __syncthreads();

        float acc[4][8][4];
#pragma unroll
        for (int mi = 0; mi < 4; ++mi)
#pragma unroll
            for (int ni = 0; ni < 8; ++ni)
#pragma unroll
                for (int v = 0; v < 4; ++v) acc[mi][ni][v] = 0.0f;

        issue_stage(m0, n0, 0, 0, sbase, tid);
        issue_stage(m0, n0, 1, 1, sbase, tid);

        for (int kt = 0; kt < NKT; ++kt) {
            const int rem = NKT - 1 - kt;
            if (rem >= STAGES - 2) {
                asm volatile("cp.async.wait_group %0;\n" :: "n"(STAGES - 2) : "memory");
            } else {
                asm volatile("cp.async.wait_group 0;\n" ::: "memory");
            }
            __syncthreads();

            const int nk = kt + STAGES - 1;
            if (nk < NKT)
                issue_stage(m0, n0, nk, nk % STAGES, sbase, tid);

            const uint32_t sA = sbase + (uint32_t)((kt % STAGES) * STAGE_BYTES);
            const uint32_t sB = sA + A_BYTES;

            // double-buffered fragments: load step s+1 while computing step s
            uint32_t a[2][4][4];
            uint32_t bf[2][4][4];
#pragma unroll
            for (int mi = 0; mi < 4; ++mi)
                ldsm4(a[0][mi], sA + sw_off(wm * 64 + mi * 16 + a_row, a_cofs));
#pragma unroll
            for (int j = 0; j < 4; ++j)
                ldsm4(bf[0][j], sB + sw_off(wn * 64 + j * 16 + b_row, b_cofs));

#pragma unroll
            for (int s = 0; s < TKH / 16; ++s) {   // 4 k16 steps
                const int cur = s & 1;
                const int nxt = cur ^ 1;
                if (s < TKH / 16 - 1) {
#pragma unroll
                    for (int mi = 0; mi < 4; ++mi)
                        ldsm4(a[nxt][mi],
                              sA + sw_off(wm * 64 + mi * 16 + a_row, 2 * (s + 1) + a_cofs));
#pragma unroll
                    for (int j = 0; j < 4; ++j)
                        ldsm4(bf[nxt][j],
                              sB + sw_off(wn * 64 + j * 16 + b_row, 2 * (s + 1) + b_cofs));
                }
#pragma unroll
                for (int mi = 0; mi < 4; ++mi)
#pragma unroll
                    for (int ni = 0; ni < 8; ++ni)
                        mma_f16(acc[mi][ni], a[cur][mi], &bf[cur][ni >> 1][(ni & 1) * 2]);
            }
        }

        // epilogue
#pragma unroll
        for (int mi = 0; mi < 4; ++mi) {
            const int m = m0 + wm * 64 + mi * 16 + g;
#pragma unroll
            for (int ni = 0; ni < 8; ++ni) {
                const int n = n0 + wn * 64 + ni * 8 + nc2;
                const float2 bb = *(const float2*)(bias + n);
                float2 o0, o1;
                o0.x = acc[mi][ni][0] + bb.x;
                o0.y = acc[mi][ni][1] + bb.y;
                o1.x = acc[mi][ni][2] + bb.x;
                o1.y = acc[mi][ni][3] + bb.y;
                *(float2*)(out + (size_t)m * DD + n) = o0;
                *(float2*)(out + (size_t)(m + 8) * DD + n) = o1;
            }
        }
        __syncthreads();
    }
}

// ---------------------------------------------------------------------------
extern "C" void kernel_launch(void* const* d_in, const int* in_sizes, int n_in,
                              void* d_out, int out_size) {
    const float* x = (const float*)d_in[0];   // [4,2048,4096] -> M=8192
    const float* W = (const float*)d_in[1];   // [4096,4096]
    const float* b = (const float*)d_in[2];   // [4096]
    float* out = (float*)d_out;

    cudaFuncSetAttribute(fused_kernel,
                         cudaFuncAttributeMaxDynamicSharedMemorySize, SMEM_TOTAL);

    fused_kernel<<<GRID, NTHREADS, SMEM_TOTAL>>>(W, x, b, out);
}

// round 12
// speedup vs baseline: 1.3214x; 1.3214x over previous
#include <cuda_runtime.h>
#include <cuda_fp16.h>
#include <cstdint>
#include <cstddef>

#define DD 4096
#define MM 8192

// Scratch: Hadamard-rotated fp16 W [N,K]; fp16 x [M,K].
__device__ __align__(256) __half g_Wh[(size_t)DD * DD];
__device__ __align__(256) __half g_Xh[(size_t)MM * DD];

// ---------------------------------------------------------------------------
// Kernel 1 (fused prep, 128-thread blocks):
//   blocks [0, 4096):        row-wise WHT of W (32 elem/thread: 5 reg + 5
//                            shfl + 2 smem stages), scale 1/64, round fp16
//   blocks [4096, 4096+16384): convert x to fp16 (16 floats/thread)
// (xH)W^T == x(WH)^T since H is symmetric.
// ---------------------------------------------------------------------------
constexpr int PREP_THREADS = 128;
constexpr int CVT_BLOCKS = (MM * DD) / (PREP_THREADS * 16);   // 16384

__global__ void prep_kernel(const float* __restrict__ W,
                            const float4* __restrict__ x) {
    const int tid = threadIdx.x;
    if (blockIdx.x < DD) {
        __shared__ float sh[DD];
        const int lane = tid & 31;
        const int r = blockIdx.x;
        float v[32];
        const float4* src = (const float4*)(W + (size_t)r * DD) + tid * 8;
#pragma unroll
        for (int j = 0; j < 8; ++j) {
            float4 u = src[j];
            v[4 * j] = u.x; v[4 * j + 1] = u.y;
            v[4 * j + 2] = u.z; v[4 * j + 3] = u.w;
        }
        // stages len=1..16: in registers (32 contiguous elements per thread)
#pragma unroll
        for (int len = 1; len <= 16; len <<= 1) {
#pragma unroll
            for (int e = 0; e < 32; ++e) {
                if ((e & len) == 0) {
                    float a = v[e], b = v[e | len];
                    v[e] = a + b;
                    v[e | len] = a - b;
                }
            }
        }
        // stages len=32..512: shfl.bfly across lanes (mask = len/32)
#pragma unroll
        for (int m = 1; m <= 16; m <<= 1) {
#pragma unroll
            for (int e = 0; e < 32; ++e) {
                float rr = __shfl_xor_sync(0xffffffffu, v[e], m);
                v[e] = (lane & m) ? (rr - v[e]) : (v[e] + rr);
            }
        }
        // stages len=1024,2048: cross-warp via smem (partner thread ^32, ^64)
#pragma unroll
        for (int mw = 32; mw <= 64; mw <<= 1) {
            __syncthreads();
#pragma unroll
            for (int e = 0; e < 32; ++e) sh[tid * 32 + e] = v[e];
            __syncthreads();
            const int p = (tid ^ mw) * 32;
#pragma unroll
            for (int e = 0; e < 32; ++e) {
                float rr = sh[p + e];
                v[e] = (tid & mw) ? (rr - v[e]) : (v[e] + rr);
            }
        }
        // scale, convert, store 32 halves (4x uint4)
        uint4* dst = (uint4*)(g_Wh + (size_t)r * DD + tid * 32);
#pragma unroll
        for (int j = 0; j < 4; ++j) {
            __half2 h0 = __floats2half2_rn(v[8 * j] * 0.015625f, v[8 * j + 1] * 0.015625f);
            __half2 h1 = __floats2half2_rn(v[8 * j + 2] * 0.015625f, v[8 * j + 3] * 0.015625f);
            __half2 h2 = __floats2half2_rn(v[8 * j + 4] * 0.015625f, v[8 * j + 5] * 0.015625f);
            __half2 h3 = __floats2half2_rn(v[8 * j + 6] * 0.015625f, v[8 * j + 7] * 0.015625f);
            uint4 o;
            o.x = *(uint32_t*)&h0; o.y = *(uint32_t*)&h1;
            o.z = *(uint32_t*)&h2; o.w = *(uint32_t*)&h3;
            dst[j] = o;
        }
    } else {
        // x convert: 16 floats per thread (4 float4 in, 2 uint4 out)
        const size_t base = ((size_t)(blockIdx.x - DD) * PREP_THREADS + tid) * 4;
#pragma unroll
        for (int u = 0; u < 2; ++u) {
            float4 v0 = x[base + 2 * u];
            float4 v1 = x[base + 2 * u + 1];
            __half2 h0 = __floats2half2_rn(v0.x, v0.y);
            __half2 h1 = __floats2half2_rn(v0.z, v0.w);
            __half2 h2 = __floats2half2_rn(v1.x, v1.y);
            __half2 h3 = __floats2half2_rn(v1.z, v1.w);
            uint4 o;
            o.x = *(uint32_t*)&h0; o.y = *(uint32_t*)&h1;
            o.z = *(uint32_t*)&h2; o.w = *(uint32_t*)&h3;
            ((uint4*)g_Xh)[base / 2 + u] = o;
        }
    }
}

// ---------------------------------------------------------------------------
// Kernel 2: fp16 mma.sync GEMM  out[M,N] = Xh[M,K] @ Wh[N,K]^T + bias
// CTA 128x128, 4 warps (2x2), warp tile 64x64, TKH=64 (128B rows),
// 3-stage cp.async, XOR-swizzled smem, 2 CTAs/SM, fragments double-buffered.
// (Round-8 configuration: best measured GEMM = 611 us.)
// ---------------------------------------------------------------------------
constexpr int TM = 128;
constexpr int TN = 128;
constexpr int TKH = 64;                      // halves per K-tile (128 B)
constexpr int NKT = DD / TKH;                // 64
constexpr int STAGES = 3;
constexpr int A_BYTES = TM * 128;            // 16384
constexpr int B_BYTES = TN * 128;            // 16384
constexpr int STAGE_BYTES = A_BYTES + B_BYTES;          // 32768
constexpr int SMEM_TOTAL = STAGES * STAGE_BYTES;        // 98304
constexpr int NTHREADS = 128;

__device__ __forceinline__ uint32_t smem_u32(const void* p) {
    return (uint32_t)__cvta_generic_to_shared(p);
}
__device__ __forceinline__ void cp16(uint32_t dst, const void* src) {
    asm volatile("cp.async.cg.shared.global [%0], [%1], 16;\n" :: "r"(dst), "l"(src));
}
__device__ __forceinline__ void ldsm4(uint32_t* r, uint32_t addr) {
    asm volatile("ldmatrix.sync.aligned.m8n8.x4.shared.b16 {%0,%1,%2,%3}, [%4];"
                 : "=r"(r[0]), "=r"(r[1]), "=r"(r[2]), "=r"(r[3]) : "r"(addr));
}
__device__ __forceinline__ void mma_f16(float* c, const uint32_t* a, const uint32_t* b) {
    asm volatile(
        "mma.sync.aligned.m16n8k16.row.col.f32.f16.f16.f32 "
        "{%0,%1,%2,%3}, {%4,%5,%6,%7}, {%8,%9}, {%0,%1,%2,%3};"
        : "+f"(c[0]), "+f"(c[1]), "+f"(c[2]), "+f"(c[3])
        : "r"(a[0]), "r"(a[1]), "r"(a[2]), "r"(a[3]),
          "r"(b[0]), "r"(b[1]));
}

// swizzled byte offset inside a 128B-wide tile
__device__ __forceinline__ uint32_t sw_off(int row, int chunk) {
    return (uint32_t)(row * 128 + ((chunk ^ (row & 7)) << 4));
}

__device__ __forceinline__ void issue_stage(int m0, int n0, int kt, int slot,
                                            uint32_t sbase, int tid) {
    const uint32_t stA = sbase + (uint32_t)(slot * STAGE_BYTES);
    const uint32_t stB = stA + A_BYTES;
    const __half* gA = g_Xh + (size_t)m0 * DD + kt * TKH;
    const __half* gB = g_Wh + (size_t)n0 * DD + kt * TKH;
#pragma unroll
    for (int i = 0; i < 8; ++i) {            // A: 1024 16B chunks
        const int idx = tid + i * NTHREADS;
        const int row = idx >> 3;
        const int c = idx & 7;
        cp16(stA + sw_off(row, c), gA + (size_t)row * DD + c * 8);
    }
#pragma unroll
    for (int i = 0; i < 8; ++i) {            // B: 1024 16B chunks
        const int idx = tid + i * NTHREADS;
        const int row = idx >> 3;
        const int c = idx & 7;
        cp16(stB + sw_off(row, c), gB + (size_t)row * DD + c * 8);
    }
    asm volatile("cp.async.commit_group;\n" ::: "memory");
}

__global__ void __launch_bounds__(NTHREADS, 2)
gemm_f16_kernel(const float* __restrict__ bias, float* __restrict__ out) {
    extern __shared__ char smem[];
    const uint32_t sbase = smem_u32(smem);
    const int tid = threadIdx.x;
    const int wid = tid >> 5;
    const int lane = tid & 31;
    const int g = lane >> 2;              // accumulator row within 8
    const int nc2 = (lane & 3) * 2;       // accumulator n-col base
    const int wm = wid & 1;               // 2 warps along M (64 rows each)
    const int wn = wid >> 1;              // 2 warps along N (64 cols each)

    // per-lane ldmatrix row/chunk components
    const int a_row = lane & 15;
    const int a_cofs = lane >> 4;                       // 0/1
    const int b_row = ((lane >> 4) << 3) + (lane & 7);
    const int b_cofs = (lane >> 3) & 1;                 // 0/1

    // CTA swizzle: groups of 16 M-tiles sweep all 32 N-tiles (L2 locality)
    constexpr int PN = DD / TN;           // 32
    constexpr int G = 16;
    const int pid = blockIdx.x;
    const int grp = pid / (G * PN);
    const int pm = grp * G + (pid % G);
    const int pn = (pid % (G * PN)) / G;
    const int m0 = pm * TM;
    const int n0 = pn * TN;

    float acc[4][8][4];
#pragma unroll
    for (int mi = 0; mi < 4; ++mi)
#pragma unroll
        for (int ni = 0; ni < 8; ++ni)
#pragma unroll
            for (int v = 0; v < 4; ++v) acc[mi][ni][v] = 0.0f;

#pragma unroll
    for (int kt = 0; kt < STAGES - 1; ++kt)
        issue_stage(m0, n0, kt, kt, sbase, tid);

    for (int kt = 0; kt < NKT; ++kt) {
        const int rem = NKT - 1 - kt;
        if (rem >= STAGES - 2) {
            asm volatile("cp.async.wait_group %0;\n" :: "n"(STAGES - 2) : "memory");
        } else {
            asm volatile("cp.async.wait_group 0;\n" ::: "memory");
        }
        __syncthreads();

        const int nk = kt + STAGES - 1;
        if (nk < NKT)
            issue_stage(m0, n0, nk, nk % STAGES, sbase, tid);

        const uint32_t sA = sbase + (uint32_t)((kt % STAGES) * STAGE_BYTES);
        const uint32_t sB = sA + A_BYTES;

        // double-buffered fragments: load step s+1 while computing step s
        uint32_t a[2][4][4];
        uint32_t bf[2][4][4];
#pragma unroll
        for (int mi = 0; mi < 4; ++mi)
            ldsm4(a[0][mi], sA + sw_off(wm * 64 + mi * 16 + a_row, a_cofs));
#pragma unroll
        for (int j = 0; j < 4; ++j)
            ldsm4(bf[0][j], sB + sw_off(wn * 64 + j * 16 + b_row, b_cofs));

#pragma unroll
        for (int s = 0; s < TKH / 16; ++s) {   // 4 k16 steps
            const int cur = s & 1;
            const int nxt = cur ^ 1;
            if (s < TKH / 16 - 1) {
#pragma unroll
                for (int mi = 0; mi < 4; ++mi)
                    ldsm4(a[nxt][mi],
                          sA + sw_off(wm * 64 + mi * 16 + a_row, 2 * (s + 1) + a_cofs));
#pragma unroll
                for (int j = 0; j < 4; ++j)
                    ldsm4(bf[nxt][j],
                          sB + sw_off(wn * 64 + j * 16 + b_row, 2 * (s + 1) + b_cofs));
            }
#pragma unroll
            for (int mi = 0; mi < 4; ++mi)
#pragma unroll
                for (int ni = 0; ni < 8; ++ni)
                    mma_f16(acc[mi][ni], a[cur][mi], &bf[cur][ni >> 1][(ni & 1) * 2]);
        }
    }

    // epilogue
#pragma unroll
    for (int mi = 0; mi < 4; ++mi) {
        const int m = m0 + wm * 64 + mi * 16 + g;
#pragma unroll
        for (int ni = 0; ni < 8; ++ni) {
            const int n = n0 + wn * 64 + ni * 8 + nc2;
            const float2 bb = *(const float2*)(bias + n);
            float2 o0, o1;
            o0.x = acc[mi][ni][0] + bb.x;
            o0.y = acc[mi][ni][1] + bb.y;
            o1.x = acc[mi][ni][2] + bb.x;
            o1.y = acc[mi][ni][3] + bb.y;
            *(float2*)(out + (size_t)m * DD + n) = o0;
            *(float2*)(out + (size_t)(m + 8) * DD + n) = o1;
        }
    }
}

// ---------------------------------------------------------------------------
extern "C" void kernel_launch(void* const* d_in, const int* in_sizes, int n_in,
                              void* d_out, int out_size) {
    const float* x = (const float*)d_in[0];   // [4,2048,4096] -> M=8192
    const float* W = (const float*)d_in[1];   // [4096,4096]
    const float* b = (const float*)d_in[2];   // [4096]
    float* out = (float*)d_out;

    cudaFuncSetAttribute(gemm_f16_kernel,
                         cudaFuncAttributeMaxDynamicSharedMemorySize, SMEM_TOTAL);

    prep_kernel<<<DD + CVT_BLOCKS, PREP_THREADS>>>(W, (const float4*)x);

    const int grid = (MM / TM) * (DD / TN);   // 64 * 32 = 2048
    gemm_f16_kernel<<<grid, NTHREADS, SMEM_TOTAL>>>(b, out);
}

// round 13
// speedup vs baseline: 1.4147x; 1.0706x over previous
#include <cuda_runtime.h>
#include <cuda_fp16.h>
#include <cstdint>
#include <cstddef>

#define DD 4096
#define MM 8192

// Scratch: Hadamard-rotated fp16 W [N,K]; fp16 x [M,K].
__device__ __align__(256) __half g_Wh[(size_t)DD * DD];
__device__ __align__(256) __half g_Xh[(size_t)MM * DD];

// ---------------------------------------------------------------------------
// Kernel 1 (fused prep, 128-thread blocks):
//   blocks [0, 4096):         row-wise WHT of W: 32 elem/thread, 5 reg + 5
//                             shfl + 2 smem stages with stride-33 padding
//                             (bank-conflict-free), scale 1/64, round fp16
//   blocks [4096, 4096+8192): convert x to fp16 (32 floats/thread, coalesced)
// (xH)W^T == x(WH)^T since H is symmetric.
// ---------------------------------------------------------------------------
constexpr int PREP_THREADS = 128;
constexpr int CVT_BLOCKS = (MM * DD) / (PREP_THREADS * 32);   // 8192

__global__ void prep_kernel(const float* __restrict__ W,
                            const float4* __restrict__ x) {
    const int tid = threadIdx.x;
    if (blockIdx.x < DD) {
        __shared__ float sh[PREP_THREADS * 33];   // stride-33 pad: conflict-free
        const int lane = tid & 31;
        const int r = blockIdx.x;
        float v[32];
        const float4* src = (const float4*)(W + (size_t)r * DD) + tid * 8;
#pragma unroll
        for (int j = 0; j < 8; ++j) {
            float4 u = src[j];
            v[4 * j] = u.x; v[4 * j + 1] = u.y;
            v[4 * j + 2] = u.z; v[4 * j + 3] = u.w;
        }
        // stages len=1..16: in registers (32 contiguous elements per thread)
#pragma unroll
        for (int len = 1; len <= 16; len <<= 1) {
#pragma unroll
            for (int e = 0; e < 32; ++e) {
                if ((e & len) == 0) {
                    float a = v[e], b = v[e | len];
                    v[e] = a + b;
                    v[e | len] = a - b;
                }
            }
        }
        // stages len=32..512: shfl.bfly across lanes (mask = len/32)
#pragma unroll
        for (int m = 1; m <= 16; m <<= 1) {
#pragma unroll
            for (int e = 0; e < 32; ++e) {
                float rr = __shfl_xor_sync(0xffffffffu, v[e], m);
                v[e] = (lane & m) ? (rr - v[e]) : (v[e] + rr);
            }
        }
        // stages len=1024,2048: cross-warp via padded smem (partner ^32, ^64)
#pragma unroll
        for (int mw = 32; mw <= 64; mw <<= 1) {
            __syncthreads();
#pragma unroll
            for (int e = 0; e < 32; ++e) sh[tid * 33 + e] = v[e];
            __syncthreads();
            const int p = (tid ^ mw) * 33;
#pragma unroll
            for (int e = 0; e < 32; ++e) {
                float rr = sh[p + e];
                v[e] = (tid & mw) ? (rr - v[e]) : (v[e] + rr);
            }
        }
        // scale, convert, store 32 halves (4x uint4)
        uint4* dst = (uint4*)(g_Wh + (size_t)r * DD + tid * 32);
#pragma unroll
        for (int j = 0; j < 4; ++j) {
            __half2 h0 = __floats2half2_rn(v[8 * j] * 0.015625f, v[8 * j + 1] * 0.015625f);
            __half2 h1 = __floats2half2_rn(v[8 * j + 2] * 0.015625f, v[8 * j + 3] * 0.015625f);
            __half2 h2 = __floats2half2_rn(v[8 * j + 4] * 0.015625f, v[8 * j + 5] * 0.015625f);
            __half2 h3 = __floats2half2_rn(v[8 * j + 6] * 0.015625f, v[8 * j + 7] * 0.015625f);
            uint4 o;
            o.x = *(uint32_t*)&h0; o.y = *(uint32_t*)&h1;
            o.z = *(uint32_t*)&h2; o.w = *(uint32_t*)&h3;
            dst[j] = o;
        }
    } else {
        // x convert: 32 floats/thread, 4 iters x (2 adjacent float4 -> 1 uint4)
        const size_t b4 = (size_t)(blockIdx.x - DD) * (PREP_THREADS * 8);
#pragma unroll
        for (int it = 0; it < 4; ++it) {
            const size_t i4 = b4 + (size_t)it * (PREP_THREADS * 2) + tid * 2;
            float4 v0 = x[i4];
            float4 v1 = x[i4 + 1];
            __half2 h0 = __floats2half2_rn(v0.x, v0.y);
            __half2 h1 = __floats2half2_rn(v0.z, v0.w);
            __half2 h2 = __floats2half2_rn(v1.x, v1.y);
            __half2 h3 = __floats2half2_rn(v1.z, v1.w);
            uint4 o;
            o.x = *(uint32_t*)&h0; o.y = *(uint32_t*)&h1;
            o.z = *(uint32_t*)&h2; o.w = *(uint32_t*)&h3;
            ((uint4*)g_Xh)[i4 / 2] = o;
        }
    }
}

// ---------------------------------------------------------------------------
// Kernel 2: fp16 mma.sync GEMM  out[M,N] = Xh[M,K] @ Wh[N,K]^T + bias
// CTA 128x128, 4 warps (2x2), warp tile 64x64, TKH=64 (128B rows),
// 3-stage cp.async, XOR-swizzled smem, 2 CTAs/SM, fragments double-buffered.
// (Round-8 configuration: best measured GEMM = 611 us.)
// ---------------------------------------------------------------------------
constexpr int TM = 128;
constexpr int TN = 128;
constexpr int TKH = 64;                      // halves per K-tile (128 B)
constexpr int NKT = DD / TKH;                // 64
constexpr int STAGES = 3;
constexpr int A_BYTES = TM * 128;            // 16384
constexpr int B_BYTES = TN * 128;            // 16384
constexpr int STAGE_BYTES = A_BYTES + B_BYTES;          // 32768
constexpr int SMEM_TOTAL = STAGES * STAGE_BYTES;        // 98304
constexpr int NTHREADS = 128;

__device__ __forceinline__ uint32_t smem_u32(const void* p) {
    return (uint32_t)__cvta_generic_to_shared(p);
}
__device__ __forceinline__ void cp16(uint32_t dst, const void* src) {
    asm volatile("cp.async.cg.shared.global [%0], [%1], 16;\n" :: "r"(dst), "l"(src));
}
__device__ __forceinline__ void ldsm4(uint32_t* r, uint32_t addr) {
    asm volatile("ldmatrix.sync.aligned.m8n8.x4.shared.b16 {%0,%1,%2,%3}, [%4];"
                 : "=r"(r[0]), "=r"(r[1]), "=r"(r[2]), "=r"(r[3]) : "r"(addr));
}
__device__ __forceinline__ void mma_f16(float* c, const uint32_t* a, const uint32_t* b) {
    asm volatile(
        "mma.sync.aligned.m16n8k16.row.col.f32.f16.f16.f32 "
        "{%0,%1,%2,%3}, {%4,%5,%6,%7}, {%8,%9}, {%0,%1,%2,%3};"
        : "+f"(c[0]), "+f"(c[1]), "+f"(c[2]), "+f"(c[3])
        : "r"(a[0]), "r"(a[1]), "r"(a[2]), "r"(a[3]),
          "r"(b[0]), "r"(b[1]));
}

// swizzled byte offset inside a 128B-wide tile
__device__ __forceinline__ uint32_t sw_off(int row, int chunk) {
    return (uint32_t)(row * 128 + ((chunk ^ (row & 7)) << 4));
}

__device__ __forceinline__ void issue_stage(int m0, int n0, int kt, int slot,
                                            uint32_t sbase, int tid) {
    const uint32_t stA = sbase + (uint32_t)(slot * STAGE_BYTES);
    const uint32_t stB = stA + A_BYTES;
    const __half* gA = g_Xh + (size_t)m0 * DD + kt * TKH;
    const __half* gB = g_Wh + (size_t)n0 * DD + kt * TKH;
#pragma unroll
    for (int i = 0; i < 8; ++i) {            // A: 1024 16B chunks
        const int idx = tid + i * NTHREADS;
        const int row = idx >> 3;
        const int c = idx & 7;
        cp16(stA + sw_off(row, c), gA + (size_t)row * DD + c * 8);
    }
#pragma unroll
    for (int i = 0; i < 8; ++i) {            // B: 1024 16B chunks
        const int idx = tid + i * NTHREADS;
        const int row = idx >> 3;
        const int c = idx & 7;
        cp16(stB + sw_off(row, c), gB + (size_t)row * DD + c * 8);
    }
    asm volatile("cp.async.commit_group;\n" ::: "memory");
}

__global__ void __launch_bounds__(NTHREADS, 2)
gemm_f16_kernel(const float* __restrict__ bias, float* __restrict__ out) {
    extern __shared__ char smem[];
    const uint32_t sbase = smem_u32(smem);
    const int tid = threadIdx.x;
    const int wid = tid >> 5;
    const int lane = tid & 31;
    const int g = lane >> 2;              // accumulator row within 8
    const int nc2 = (lane & 3) * 2;       // accumulator n-col base
    const int wm = wid & 1;               // 2 warps along M (64 rows each)
    const int wn = wid >> 1;              // 2 warps along N (64 cols each)

    // per-lane ldmatrix row/chunk components
    const int a_row = lane & 15;
    const int a_cofs = lane >> 4;                       // 0/1
    const int b_row = ((lane >> 4) << 3) + (lane & 7);
    const int b_cofs = (lane >> 3) & 1;                 // 0/1

    // CTA swizzle: groups of 16 M-tiles sweep all 32 N-tiles (L2 locality)
    constexpr int PN = DD / TN;           // 32
    constexpr int G = 16;
    const int pid = blockIdx.x;
    const int grp = pid / (G * PN);
    const int pm = grp * G + (pid % G);
    const int pn = (pid % (G * PN)) / G;
    const int m0 = pm * TM;
    const int n0 = pn * TN;

    float acc[4][8][4];
#pragma unroll
    for (int mi = 0; mi < 4; ++mi)
#pragma unroll
        for (int ni = 0; ni < 8; ++ni)
#pragma unroll
            for (int v = 0; v < 4; ++v) acc[mi][ni][v] = 0.0f;

#pragma unroll
    for (int kt = 0; kt < STAGES - 1; ++kt)
        issue_stage(m0, n0, kt, kt, sbase, tid);

    for (int kt = 0; kt < NKT; ++kt) {
        const int rem = NKT - 1 - kt;
        if (rem >= STAGES - 2) {
            asm volatile("cp.async.wait_group %0;\n" :: "n"(STAGES - 2) : "memory");
        } else {
            asm volatile("cp.async.wait_group 0;\n" ::: "memory");
        }
        __syncthreads();

        const int nk = kt + STAGES - 1;
        if (nk < NKT)
            issue_stage(m0, n0, nk, nk % STAGES, sbase, tid);

        const uint32_t sA = sbase + (uint32_t)((kt % STAGES) * STAGE_BYTES);
        const uint32_t sB = sA + A_BYTES;

        // double-buffered fragments: load step s+1 while computing step s
        uint32_t a[2][4][4];
        uint32_t bf[2][4][4];
#pragma unroll
        for (int mi = 0; mi < 4; ++mi)
            ldsm4(a[0][mi], sA + sw_off(wm * 64 + mi * 16 + a_row, a_cofs));
#pragma unroll
        for (int j = 0; j < 4; ++j)
            ldsm4(bf[0][j], sB + sw_off(wn * 64 + j * 16 + b_row, b_cofs));

#pragma unroll
        for (int s = 0; s < TKH / 16; ++s) {   // 4 k16 steps
            const int cur = s & 1;
            const int nxt = cur ^ 1;
            if (s < TKH / 16 - 1) {
#pragma unroll
                for (int mi = 0; mi < 4; ++mi)
                    ldsm4(a[nxt][mi],
                          sA + sw_off(wm * 64 + mi * 16 + a_row, 2 * (s + 1) + a_cofs));
#pragma unroll
                for (int j = 0; j < 4; ++j)
                    ldsm4(bf[nxt][j],
                          sB + sw_off(wn * 64 + j * 16 + b_row, 2 * (s + 1) + b_cofs));
            }
#pragma unroll
            for (int mi = 0; mi < 4; ++mi)
#pragma unroll
                for (int ni = 0; ni < 8; ++ni)
                    mma_f16(acc[mi][ni], a[cur][mi], &bf[cur][ni >> 1][(ni & 1) * 2]);
        }
    }

    // epilogue
#pragma unroll
    for (int mi = 0; mi < 4; ++mi) {
        const int m = m0 + wm * 64 + mi * 16 + g;
#pragma unroll
        for (int ni = 0; ni < 8; ++ni) {
            const int n = n0 + wn * 64 + ni * 8 + nc2;
            const float2 bb = *(const float2*)(bias + n);
            float2 o0, o1;
            o0.x = acc[mi][ni][0] + bb.x;
            o0.y = acc[mi][ni][1] + bb.y;
            o1.x = acc[mi][ni][2] + bb.x;
            o1.y = acc[mi][ni][3] + bb.y;
            *(float2*)(out + (size_t)m * DD + n) = o0;
            *(float2*)(out + (size_t)(m + 8) * DD + n) = o1;
        }
    }
}

// ---------------------------------------------------------------------------
extern "C" void kernel_launch(void* const* d_in, const int* in_sizes, int n_in,
                              void* d_out, int out_size) {
    const float* x = (const float*)d_in[0];   // [4,2048,4096] -> M=8192
    const float* W = (const float*)d_in[1];   // [4096,4096]
    const float* b = (const float*)d_in[2];   // [4096]
    float* out = (float*)d_out;

    cudaFuncSetAttribute(gemm_f16_kernel,
                         cudaFuncAttributeMaxDynamicSharedMemorySize, SMEM_TOTAL);

    prep_kernel<<<DD + CVT_BLOCKS, PREP_THREADS>>>(W, (const float4*)x);

    const int grid = (MM / TM) * (DD / TN);   // 64 * 32 = 2048
    gemm_f16_kernel<<<grid, NTHREADS, SMEM_TOTAL>>>(b, out);
}